// round 11
// baseline (speedup 1.0000x reference)
#include <cuda_runtime.h>
#include <cuda_bf16.h>

#define NPTS 4096
#define NF   (NPTS - 2)
#define EPSF 1e-8f
#define LT   256
#define FRB  8                       // frames per block (4 packed pairs)
#define CHUNK 1024                   // points per block
#define NBLK ((NPTS / FRB) * (NPTS / CHUNK))   // 512 x 4 = 2048

typedef unsigned long long u64;

// Scratch (device globals only — allocations forbidden)
// Point data pre-duplicated for f32x2: rows 0..2 = (-p,-p).{x,y,z}, 3..5 = (q,q).{x,y,z}
__device__ __align__(16) u64 g_pd[6][NPTS];
// Fused frame constants, SoA over frames (padded to 4096):
// k=0..8: M = Rp^T * Rt (row-major), k=9..11: c = op - M*ot
__device__ __align__(16) float g_fc[12][NPTS];
__device__ double g_acc;
__device__ unsigned g_tick;

__device__ __forceinline__ float rsqrt_fast(float x) {
    float y; asm("rsqrt.approx.f32 %0, %1;" : "=f"(y) : "f"(x)); return y;
}
__device__ __forceinline__ float sqrt_fast(float x) {
    float y; asm("sqrt.approx.f32 %0, %1;" : "=f"(y) : "f"(x)); return y;
}
__device__ __forceinline__ u64 dupf(float a) {
    u64 r; asm("mov.b64 %0, {%1, %1};" : "=l"(r) : "f"(a)); return r;
}
__device__ __forceinline__ u64 ffma2(u64 a, u64 b, u64 c) {
    u64 d; asm("fma.rn.f32x2 %0, %1, %2, %3;" : "=l"(d) : "l"(a), "l"(b), "l"(c));
    return d;
}
__device__ __forceinline__ u64 fadd2(u64 a, u64 b) {
    u64 d; asm("add.rn.f32x2 %0, %1, %2;" : "=l"(d) : "l"(a), "l"(b));
    return d;
}
__device__ __forceinline__ void unpk(u64 v, float& lo, float& hi) {
    asm("mov.b64 {%0, %1}, %2;" : "=f"(lo), "=f"(hi) : "l"(v));
}

__device__ __forceinline__ void build_frame(const float* __restrict__ c, int i,
                                            float* __restrict__ R, float* __restrict__ o) {
    float ox = c[3*i+3], oy = c[3*i+4], oz = c[3*i+5];
    float ax = c[3*i+6] - ox, ay = c[3*i+7] - oy, az = c[3*i+8] - oz;
    float i1 = rsqrt_fast(ax*ax + ay*ay + az*az);
    ax *= i1; ay *= i1; az *= i1;
    float bx = c[3*i] - ox, by = c[3*i+1] - oy, bz = c[3*i+2] - oz;
    float d = bx*ax + by*ay + bz*az;
    bx -= d*ax; by -= d*ay; bz -= d*az;
    float i2 = rsqrt_fast(bx*bx + by*by + bz*bz);
    bx *= i2; by *= i2; bz *= i2;
    R[0]=ax; R[1]=ay; R[2]=az;
    R[3]=bx; R[4]=by; R[5]=bz;
    R[6]=ay*bz - az*by; R[7]=az*bx - ax*bz; R[8]=ax*by - ay*bx;
    o[0]=ox; o[1]=oy; o[2]=oz;
}

__global__ void prep_kernel(const float* __restrict__ pred, const float* __restrict__ tru) {
    int i = blockIdx.x * blockDim.x + threadIdx.x;
    if (i == 0) g_acc = 0.0;
    if (i < NPTS) {
        g_pd[0][i] = dupf(-pred[3*i]);
        g_pd[1][i] = dupf(-pred[3*i+1]);
        g_pd[2][i] = dupf(-pred[3*i+2]);
        g_pd[3][i] = dupf(tru[3*i]);
        g_pd[4][i] = dupf(tru[3*i+1]);
        g_pd[5][i] = dupf(tru[3*i+2]);
    }
    if (i < NF) {
        float Rp[9], op[3], Rt[9], ot[3];
        build_frame(pred, i, Rp, op);
        build_frame(tru,  i, Rt, ot);
        float M[9];
        #pragma unroll
        for (int r = 0; r < 3; r++)
            #pragma unroll
            for (int cc = 0; cc < 3; cc++)
                M[3*r+cc] = Rp[r]*Rt[cc] + Rp[3+r]*Rt[3+cc] + Rp[6+r]*Rt[6+cc];
        #pragma unroll
        for (int k = 0; k < 9; k++) g_fc[k][i] = M[k];
        #pragma unroll
        for (int r = 0; r < 3; r++)
            g_fc[9 + r][i] = op[r] - (M[3*r]*ot[0] + M[3*r+1]*ot[1] + M[3*r+2]*ot[2]);
    } else if (i < NPTS) {
        // Pad frames: dist clamps to exactly 10.0; removed analytically at the end.
        #pragma unroll
        for (int k = 0; k < 12; k++) g_fc[k][i] = 0.0f;
        g_fc[9][i] = 1e6f;
    }
}

// Each block: 8 frames (4 packed pairs, constants in SMEM) x 1024 points.
__global__ void __launch_bounds__(LT, 4) loss_kernel(float* __restrict__ out) {
    const int f  = (blockIdx.x >> 2) * FRB;
    const int n0 = (blockIdx.x & 3) * CHUNK;

    // Stage frame constants into shared memory as packed (frame, frame+1) u64 pairs.
    // Layout: sc[pair][k], k=0..8 -> M row-major, k=9..11 -> c.
    __shared__ __align__(16) u64 sc[FRB / 2][12];
    __shared__ float wsum[LT / 32];
    if (threadIdx.x < (FRB / 2) * 12) {
        int pair = threadIdx.x / 12;
        int k    = threadIdx.x % 12;
        sc[pair][k] = *(const u64*)&g_fc[k][f + 2 * pair];
    }
    __syncthreads();

    const u64 eps2 = dupf(EPSF);
    float s0 = 0.0f, s1 = 0.0f, s2 = 0.0f, s3 = 0.0f;

    const u64* __restrict__ pt = &g_pd[0][n0 + threadIdx.x];

    #pragma unroll
    for (int it = 0; it < CHUNK / LT; it++, pt += LT) {
        u64 NX = pt[0 * NPTS], NY = pt[1 * NPTS], NZ = pt[2 * NPTS];
        u64 U  = pt[3 * NPTS], V  = pt[4 * NPTS], W  = pt[5 * NPTS];

        #pragma unroll
        for (int p = 0; p < FRB / 2; p++) {
            const ulonglong2* __restrict__ cp = (const ulonglong2*)sc[p];
            ulonglong2 e0 = cp[0], e1 = cp[1], e2 = cp[2];
            ulonglong2 e3 = cp[3], e4 = cp[4], e5 = cp[5];
            // M0..M8 = e0.x,e0.y,e1.x,e1.y,e2.x,e2.y,e3.x,e3.y,e4.x ; c = e4.y,e5.x,e5.y
            u64 dx = ffma2(e0.x, U, ffma2(e0.y, V, ffma2(e1.x, W, fadd2(e4.y, NX))));
            u64 dy = ffma2(e1.y, U, ffma2(e2.x, V, ffma2(e2.y, W, fadd2(e5.x, NY))));
            u64 dz = ffma2(e3.x, U, ffma2(e3.y, V, ffma2(e4.x, W, fadd2(e5.y, NZ))));
            u64 ss = ffma2(dx, dx, ffma2(dy, dy, ffma2(dz, dz, eps2)));
            float a, b; unpk(ss, a, b);
            if (p & 1) {
                s2 += fminf(sqrt_fast(a), 10.0f);
                s3 += fminf(sqrt_fast(b), 10.0f);
            } else {
                s0 += fminf(sqrt_fast(a), 10.0f);
                s1 += fminf(sqrt_fast(b), 10.0f);
            }
        }
    }

    float sum = (s0 + s1) + (s2 + s3);
    #pragma unroll
    for (int o = 16; o > 0; o >>= 1)
        sum += __shfl_down_sync(0xffffffffu, sum, o);

    int lane = threadIdx.x & 31;
    int wid  = threadIdx.x >> 5;
    if (lane == 0) wsum[wid] = sum;
    __syncthreads();
    if (threadIdx.x == 0) {
        float v = 0.0f;
        #pragma unroll
        for (int w = 0; w < LT / 32; w++) v += wsum[w];
        atomicAdd(&g_acc, (double)v);
        __threadfence();
        unsigned t = atomicAdd(&g_tick, 1u);
        if (t == (unsigned)(NBLK - 1)) {
            double total = *((volatile double*)&g_acc);
            total -= 2.0 * (double)NPTS * 10.0;   // 2 pad frames contribute exactly 10 each
            out[0] = (float)(total / ((double)NF * (double)NPTS) / 10.0);
            g_tick = 0u;  // reset for next graph replay
        }
    }
}

extern "C" void kernel_launch(void* const* d_in, const int* in_sizes, int n_in,
                              void* d_out, int out_size) {
    const float* pred = (const float*)d_in[0];
    const float* tru  = (const float*)d_in[1];
    float* out = (float*)d_out;

    prep_kernel<<<(NPTS + 255) / 256, 256>>>(pred, tru);
    loss_kernel<<<NBLK, LT>>>(out);
}

// round 12
// speedup vs baseline: 1.7203x; 1.7203x over previous
#include <cuda_runtime.h>
#include <cuda_bf16.h>

#define NPTS 4096
#define NF   (NPTS - 2)
#define EPSF 1e-8f
#define LT   256
#define CHUNK 1024
#define NBLK ((NPTS / 4) * (NPTS / CHUNK))   // 1024 frame-groups x 4 chunks = 4096

typedef unsigned long long u64;

// Scratch (device globals only — allocations forbidden)
// Point data pre-duplicated for f32x2: rows 0..2 = (-p,-p).{x,y,z}, 3..5 = (q,q).{x,y,z}
__device__ __align__(16) u64 g_pd[6][NPTS];
// Fused frame constants, SoA over frames (padded to 4096):
// k=0..8: M = Rp^T * Rt (row-major), k=9..11: c = op - M*ot
__device__ __align__(16) float g_fc[12][NPTS];
__device__ double g_acc;
__device__ unsigned g_tick;

__device__ __forceinline__ float rsqrt_fast(float x) {
    float y; asm("rsqrt.approx.f32 %0, %1;" : "=f"(y) : "f"(x)); return y;
}
__device__ __forceinline__ float sqrt_fast(float x) {
    float y; asm("sqrt.approx.f32 %0, %1;" : "=f"(y) : "f"(x)); return y;
}
__device__ __forceinline__ u64 dupf(float a) {
    u64 r; asm("mov.b64 %0, {%1, %1};" : "=l"(r) : "f"(a)); return r;
}
__device__ __forceinline__ u64 ffma2(u64 a, u64 b, u64 c) {
    u64 d; asm("fma.rn.f32x2 %0, %1, %2, %3;" : "=l"(d) : "l"(a), "l"(b), "l"(c));
    return d;
}
__device__ __forceinline__ u64 fadd2(u64 a, u64 b) {
    u64 d; asm("add.rn.f32x2 %0, %1, %2;" : "=l"(d) : "l"(a), "l"(b));
    return d;
}
__device__ __forceinline__ void unpk(u64 v, float& lo, float& hi) {
    asm("mov.b64 {%0, %1}, %2;" : "=f"(lo), "=f"(hi) : "l"(v));
}

__device__ __forceinline__ void build_frame(const float* __restrict__ c, int i,
                                            float* __restrict__ R, float* __restrict__ o) {
    float ox = c[3*i+3], oy = c[3*i+4], oz = c[3*i+5];
    float ax = c[3*i+6] - ox, ay = c[3*i+7] - oy, az = c[3*i+8] - oz;
    float i1 = rsqrt_fast(ax*ax + ay*ay + az*az);
    ax *= i1; ay *= i1; az *= i1;
    float bx = c[3*i] - ox, by = c[3*i+1] - oy, bz = c[3*i+2] - oz;
    float d = bx*ax + by*ay + bz*az;
    bx -= d*ax; by -= d*ay; bz -= d*az;
    float i2 = rsqrt_fast(bx*bx + by*by + bz*bz);
    bx *= i2; by *= i2; bz *= i2;
    R[0]=ax; R[1]=ay; R[2]=az;
    R[3]=bx; R[4]=by; R[5]=bz;
    R[6]=ay*bz - az*by; R[7]=az*bx - ax*bz; R[8]=ax*by - ay*bx;
    o[0]=ox; o[1]=oy; o[2]=oz;
}

__global__ void prep_kernel(const float* __restrict__ pred, const float* __restrict__ tru) {
    int i = blockIdx.x * blockDim.x + threadIdx.x;
    if (i == 0) g_acc = 0.0;
    if (i < NPTS) {
        g_pd[0][i] = dupf(-pred[3*i]);
        g_pd[1][i] = dupf(-pred[3*i+1]);
        g_pd[2][i] = dupf(-pred[3*i+2]);
        g_pd[3][i] = dupf(tru[3*i]);
        g_pd[4][i] = dupf(tru[3*i+1]);
        g_pd[5][i] = dupf(tru[3*i+2]);
    }
    if (i < NF) {
        float Rp[9], op[3], Rt[9], ot[3];
        build_frame(pred, i, Rp, op);
        build_frame(tru,  i, Rt, ot);
        float M[9];
        #pragma unroll
        for (int r = 0; r < 3; r++)
            #pragma unroll
            for (int cc = 0; cc < 3; cc++)
                M[3*r+cc] = Rp[r]*Rt[cc] + Rp[3+r]*Rt[3+cc] + Rp[6+r]*Rt[6+cc];
        #pragma unroll
        for (int k = 0; k < 9; k++) g_fc[k][i] = M[k];
        #pragma unroll
        for (int r = 0; r < 3; r++)
            g_fc[9 + r][i] = op[r] - (M[3*r]*ot[0] + M[3*r+1]*ot[1] + M[3*r+2]*ot[2]);
    } else if (i < NPTS) {
        // Pad frames: dist clamps to exactly 10.0; removed analytically at the end.
        #pragma unroll
        for (int k = 0; k < 12; k++) g_fc[k][i] = 0.0f;
        g_fc[9][i] = 1e6f;
    }
}

// ss chain for one packed frame-pair against one point
__device__ __forceinline__ u64 chain_ss(u64 m0, u64 m1, u64 m2, u64 m3, u64 m4, u64 m5,
                                        u64 m6, u64 m7, u64 m8, u64 c0, u64 c1, u64 c2,
                                        u64 U, u64 V, u64 W, u64 NX, u64 NY, u64 NZ,
                                        u64 eps2) {
    u64 dx = ffma2(m0, U, ffma2(m1, V, ffma2(m2, W, fadd2(c0, NX))));
    u64 dy = ffma2(m3, U, ffma2(m4, V, ffma2(m5, W, fadd2(c1, NY))));
    u64 dz = ffma2(m6, U, ffma2(m7, V, ffma2(m8, W, fadd2(c2, NZ))));
    return ffma2(dx, dx, ffma2(dy, dy, ffma2(dz, dz, eps2)));
}

// Each block: 4 frames (pair A in registers, pair B in smem) x 1024 points,
// 2 points per thread per iteration via LDG.128 of the dup'd array.
__global__ void __launch_bounds__(LT, 4) loss_kernel(float* __restrict__ out) {
    const int f  = (blockIdx.x >> 2) * 4;
    const int n0 = (blockIdx.x & 3) * CHUNK;

    __shared__ __align__(16) u64 sB[12];
    __shared__ float wsum[LT / 32];
    if (threadIdx.x < 12)
        sB[threadIdx.x] = *(const u64*)&g_fc[threadIdx.x][f + 2];

    u64 A[12];
    #pragma unroll
    for (int k = 0; k < 12; k++)
        A[k] = *(const u64*)&g_fc[k][f];

    __syncthreads();

    const u64 eps2 = dupf(EPSF);
    float s0 = 0.0f, s1 = 0.0f, s2 = 0.0f, s3 = 0.0f;

    // ulonglong2 view: 2 consecutive points (both pre-dup'd) per 16B load.
    const ulonglong2* __restrict__ P0 = (const ulonglong2*)&g_pd[0][n0];
    const int RSTRIDE = NPTS / 2;   // row stride in ulonglong2

    #pragma unroll
    for (int it = 0; it < CHUNK / (2 * LT); it++) {
        int idx = it * LT + threadIdx.x;
        ulonglong2 nx = P0[idx + 0 * RSTRIDE];
        ulonglong2 ny = P0[idx + 1 * RSTRIDE];
        ulonglong2 nz = P0[idx + 2 * RSTRIDE];
        ulonglong2 qu = P0[idx + 3 * RSTRIDE];
        ulonglong2 qv = P0[idx + 4 * RSTRIDE];
        ulonglong2 qw = P0[idx + 5 * RSTRIDE];

        // Frame-pair A (registers), both points
        u64 ssa0 = chain_ss(A[0],A[1],A[2],A[3],A[4],A[5],A[6],A[7],A[8],A[9],A[10],A[11],
                            qu.x, qv.x, qw.x, nx.x, ny.x, nz.x, eps2);
        u64 ssa1 = chain_ss(A[0],A[1],A[2],A[3],A[4],A[5],A[6],A[7],A[8],A[9],A[10],A[11],
                            qu.y, qv.y, qw.y, nx.y, ny.y, nz.y, eps2);

        // Frame-pair B (shared memory, broadcast LDS)
        u64 ssb0 = chain_ss(sB[0],sB[1],sB[2],sB[3],sB[4],sB[5],sB[6],sB[7],sB[8],sB[9],sB[10],sB[11],
                            qu.x, qv.x, qw.x, nx.x, ny.x, nz.x, eps2);
        u64 ssb1 = chain_ss(sB[0],sB[1],sB[2],sB[3],sB[4],sB[5],sB[6],sB[7],sB[8],sB[9],sB[10],sB[11],
                            qu.y, qv.y, qw.y, nx.y, ny.y, nz.y, eps2);

        float v0, v1, v2, v3, v4, v5, v6, v7;
        unpk(ssa0, v0, v1);
        unpk(ssa1, v2, v3);
        unpk(ssb0, v4, v5);
        unpk(ssb1, v6, v7);
        s0 += fminf(sqrt_fast(v0), 10.0f);
        s1 += fminf(sqrt_fast(v1), 10.0f);
        s2 += fminf(sqrt_fast(v2), 10.0f);
        s3 += fminf(sqrt_fast(v3), 10.0f);
        s0 += fminf(sqrt_fast(v4), 10.0f);
        s1 += fminf(sqrt_fast(v5), 10.0f);
        s2 += fminf(sqrt_fast(v6), 10.0f);
        s3 += fminf(sqrt_fast(v7), 10.0f);
    }

    float sum = (s0 + s1) + (s2 + s3);
    #pragma unroll
    for (int o = 16; o > 0; o >>= 1)
        sum += __shfl_down_sync(0xffffffffu, sum, o);

    int lane = threadIdx.x & 31;
    int wid  = threadIdx.x >> 5;
    if (lane == 0) wsum[wid] = sum;
    __syncthreads();
    if (threadIdx.x == 0) {
        float v = 0.0f;
        #pragma unroll
        for (int w = 0; w < LT / 32; w++) v += wsum[w];
        atomicAdd(&g_acc, (double)v);
        __threadfence();
        unsigned t = atomicAdd(&g_tick, 1u);
        if (t == (unsigned)(NBLK - 1)) {
            double total = *((volatile double*)&g_acc);
            total -= 2.0 * (double)NPTS * 10.0;   // 2 pad frames contribute exactly 10 each
            out[0] = (float)(total / ((double)NF * (double)NPTS) / 10.0);
            g_tick = 0u;  // reset for next graph replay
        }
    }
}

extern "C" void kernel_launch(void* const* d_in, const int* in_sizes, int n_in,
                              void* d_out, int out_size) {
    const float* pred = (const float*)d_in[0];
    const float* tru  = (const float*)d_in[1];
    float* out = (float*)d_out;

    prep_kernel<<<(NPTS + 255) / 256, 256>>>(pred, tru);
    loss_kernel<<<NBLK, LT>>>(out);
}

// round 13
// speedup vs baseline: 2.9317x; 1.7042x over previous
#include <cuda_runtime.h>
#include <cuda_bf16.h>

#define NPTS 4096
#define NF   (NPTS - 2)
#define EPSF 1e-8f
#define LT   256
#define PT_CHUNK 2048
#define NBLK ((NPTS / 4) * (NPTS / PT_CHUNK))   // 1024 frame-groups x 2 chunks = 2048

typedef unsigned long long u64;

// Scratch (device globals only — allocations forbidden)
// Point data pre-duplicated for f32x2: rows 0..2 = (-p,-p).{x,y,z}, 3..5 = (q,q).{x,y,z}
__device__ __align__(16) u64 g_pd[6][NPTS];
// Fused frame constants, SoA over frames (padded to 4096):
// k=0..8: M = Rp^T * Rt (row-major), k=9..11: c = op - M*ot
__device__ __align__(16) float g_fc[12][NPTS];
__device__ double g_acc;
__device__ unsigned g_tick;

__device__ __forceinline__ float rsqrt_fast(float x) {
    float y; asm("rsqrt.approx.f32 %0, %1;" : "=f"(y) : "f"(x)); return y;
}
__device__ __forceinline__ float sqrt_fast(float x) {
    float y; asm("sqrt.approx.f32 %0, %1;" : "=f"(y) : "f"(x)); return y;
}
__device__ __forceinline__ u64 dupf(float a) {
    u64 r; asm("mov.b64 %0, {%1, %1};" : "=l"(r) : "f"(a)); return r;
}
__device__ __forceinline__ u64 ffma2(u64 a, u64 b, u64 c) {
    u64 d; asm("fma.rn.f32x2 %0, %1, %2, %3;" : "=l"(d) : "l"(a), "l"(b), "l"(c));
    return d;
}
__device__ __forceinline__ u64 fadd2(u64 a, u64 b) {
    u64 d; asm("add.rn.f32x2 %0, %1, %2;" : "=l"(d) : "l"(a), "l"(b));
    return d;
}
__device__ __forceinline__ void unpk(u64 v, float& lo, float& hi) {
    asm("mov.b64 {%0, %1}, %2;" : "=f"(lo), "=f"(hi) : "l"(v));
}

__device__ __forceinline__ void build_frame(const float* __restrict__ c, int i,
                                            float* __restrict__ R, float* __restrict__ o) {
    float ox = c[3*i+3], oy = c[3*i+4], oz = c[3*i+5];
    float ax = c[3*i+6] - ox, ay = c[3*i+7] - oy, az = c[3*i+8] - oz;
    float i1 = rsqrt_fast(ax*ax + ay*ay + az*az);
    ax *= i1; ay *= i1; az *= i1;
    float bx = c[3*i] - ox, by = c[3*i+1] - oy, bz = c[3*i+2] - oz;
    float d = bx*ax + by*ay + bz*az;
    bx -= d*ax; by -= d*ay; bz -= d*az;
    float i2 = rsqrt_fast(bx*bx + by*by + bz*bz);
    bx *= i2; by *= i2; bz *= i2;
    R[0]=ax; R[1]=ay; R[2]=az;
    R[3]=bx; R[4]=by; R[5]=bz;
    R[6]=ay*bz - az*by; R[7]=az*bx - ax*bz; R[8]=ax*by - ay*bx;
    o[0]=ox; o[1]=oy; o[2]=oz;
}

__global__ void prep_kernel(const float* __restrict__ pred, const float* __restrict__ tru) {
    int i = blockIdx.x * blockDim.x + threadIdx.x;
    if (i == 0) g_acc = 0.0;
    if (i < NPTS) {
        g_pd[0][i] = dupf(-pred[3*i]);
        g_pd[1][i] = dupf(-pred[3*i+1]);
        g_pd[2][i] = dupf(-pred[3*i+2]);
        g_pd[3][i] = dupf(tru[3*i]);
        g_pd[4][i] = dupf(tru[3*i+1]);
        g_pd[5][i] = dupf(tru[3*i+2]);
    }
    if (i < NF) {
        float Rp[9], op[3], Rt[9], ot[3];
        build_frame(pred, i, Rp, op);
        build_frame(tru,  i, Rt, ot);
        float M[9];
        #pragma unroll
        for (int r = 0; r < 3; r++)
            #pragma unroll
            for (int cc = 0; cc < 3; cc++)
                M[3*r+cc] = Rp[r]*Rt[cc] + Rp[3+r]*Rt[3+cc] + Rp[6+r]*Rt[6+cc];
        #pragma unroll
        for (int k = 0; k < 9; k++) g_fc[k][i] = M[k];
        #pragma unroll
        for (int r = 0; r < 3; r++)
            g_fc[9 + r][i] = op[r] - (M[3*r]*ot[0] + M[3*r+1]*ot[1] + M[3*r+2]*ot[2]);
    } else if (i < NPTS) {
        // Pad frames: dist clamps to exactly 10.0; removed analytically at the end.
        #pragma unroll
        for (int k = 0; k < 12; k++) g_fc[k][i] = 0.0f;
        g_fc[9][i] = 1e6f;
    }
}

// ss chain for one packed frame-pair against one point
__device__ __forceinline__ u64 chain_ss(const u64* __restrict__ A,
                                        u64 U, u64 V, u64 W,
                                        u64 NX, u64 NY, u64 NZ, u64 eps2) {
    u64 dx = ffma2(A[0], U, ffma2(A[1], V, ffma2(A[2], W, fadd2(A[9],  NX))));
    u64 dy = ffma2(A[3], U, ffma2(A[4], V, ffma2(A[5], W, fadd2(A[10], NY))));
    u64 dz = ffma2(A[6], U, ffma2(A[7], V, ffma2(A[8], W, fadd2(A[11], NZ))));
    return ffma2(dx, dx, ffma2(dy, dy, ffma2(dz, dz, eps2)));
}

// Each block: 4 frames (two packed pairs, in registers) x 2048 points.
// 2 points per thread per body via LDG.128 on the dup'd array.
__global__ void __launch_bounds__(LT, 3) loss_kernel(float* __restrict__ out) {
    const int f  = (blockIdx.x >> 1) * 4;
    const int n0 = (blockIdx.x & 1) * PT_CHUNK;

    const float* __restrict__ fc = &g_fc[0][f];
    u64 A[12], B[12];
    #pragma unroll
    for (int k = 0; k < 12; k++) {
        A[k] = *(const u64*)(fc + k * NPTS);
        B[k] = *(const u64*)(fc + k * NPTS + 2);
    }
    const u64 eps2 = dupf(EPSF);

    float s0 = 0.0f, s1 = 0.0f, s2 = 0.0f, s3 = 0.0f;

    // ulonglong2 view: one 16B load = 2 consecutive points (both pre-dup'd).
    const ulonglong2* __restrict__ P0 = (const ulonglong2*)&g_pd[0][n0];
    const int RS = NPTS / 2;   // row stride in ulonglong2

    #pragma unroll
    for (int it = 0; it < PT_CHUNK / (2 * LT); it++) {
        int idx = it * LT + threadIdx.x;
        ulonglong2 nx = P0[idx + 0 * RS];
        ulonglong2 ny = P0[idx + 1 * RS];
        ulonglong2 nz = P0[idx + 2 * RS];
        ulonglong2 qu = P0[idx + 3 * RS];
        ulonglong2 qv = P0[idx + 4 * RS];
        ulonglong2 qw = P0[idx + 5 * RS];

        // d = M*q + c - p  (sign of d irrelevant for |d|^2)
        u64 ssa0 = chain_ss(A, qu.x, qv.x, qw.x, nx.x, ny.x, nz.x, eps2);
        u64 ssb0 = chain_ss(B, qu.x, qv.x, qw.x, nx.x, ny.x, nz.x, eps2);
        u64 ssa1 = chain_ss(A, qu.y, qv.y, qw.y, nx.y, ny.y, nz.y, eps2);
        u64 ssb1 = chain_ss(B, qu.y, qv.y, qw.y, nx.y, ny.y, nz.y, eps2);

        float v0, v1, v2, v3, v4, v5, v6, v7;
        unpk(ssa0, v0, v1);
        unpk(ssb0, v2, v3);
        unpk(ssa1, v4, v5);
        unpk(ssb1, v6, v7);
        s0 += fminf(sqrt_fast(v0), 10.0f);
        s1 += fminf(sqrt_fast(v1), 10.0f);
        s2 += fminf(sqrt_fast(v2), 10.0f);
        s3 += fminf(sqrt_fast(v3), 10.0f);
        s0 += fminf(sqrt_fast(v4), 10.0f);
        s1 += fminf(sqrt_fast(v5), 10.0f);
        s2 += fminf(sqrt_fast(v6), 10.0f);
        s3 += fminf(sqrt_fast(v7), 10.0f);
    }

    float sum = (s0 + s1) + (s2 + s3);
    #pragma unroll
    for (int o = 16; o > 0; o >>= 1)
        sum += __shfl_down_sync(0xffffffffu, sum, o);

    __shared__ float wsum[LT / 32];
    int lane = threadIdx.x & 31;
    int wid  = threadIdx.x >> 5;
    if (lane == 0) wsum[wid] = sum;
    __syncthreads();
    if (threadIdx.x == 0) {
        float v = 0.0f;
        #pragma unroll
        for (int w = 0; w < LT / 32; w++) v += wsum[w];
        atomicAdd(&g_acc, (double)v);
        __threadfence();
        unsigned t = atomicAdd(&g_tick, 1u);
        if (t == (unsigned)(NBLK - 1)) {
            double total = *((volatile double*)&g_acc);
            total -= 2.0 * (double)NPTS * 10.0;   // 2 pad frames contribute exactly 10 each
            out[0] = (float)(total / ((double)NF * (double)NPTS) / 10.0);
            g_tick = 0u;  // reset for next graph replay
        }
    }
}

extern "C" void kernel_launch(void* const* d_in, const int* in_sizes, int n_in,
                              void* d_out, int out_size) {
    const float* pred = (const float*)d_in[0];
    const float* tru  = (const float*)d_in[1];
    float* out = (float*)d_out;

    prep_kernel<<<(NPTS + 255) / 256, 256>>>(pred, tru);
    loss_kernel<<<NBLK, LT>>>(out);
}